// round 12
// baseline (speedup 1.0000x reference)
#include <cuda_runtime.h>

#define NL    64
#define HH    50
#define G4    200
#define DIN   60
#define BATCH 32
#define TT    2048
#define DOUT  50
#define BS    16
#define NSL   2
#define RINGN 16
#define TPB   448   // warps 0-6: H-group (tid 0..223), warps 7-13: X-group (tid 224..447)

// ---- scratch (device globals) ----
__device__ float d_ring[(NL - 1) * RINGN * NSL * HH * BS];  // [l][slot][s][u][16]
__device__ int   d_prog[NSL * NL];
__device__ int   d_cons[NSL * NL];
__device__ float d_xT[TT * NSL * DIN * BS];                 // [t][s][d][16]
__device__ float d_hT[TT * NSL * HH * BS];                  // [t][s][u][16]

// lstm smem (floats)
#define OFF_B   0      // [200] pad 208
#define OFF_XS  208    // 2 x [60][16] double buffer
#define OFF_HS  2128   // [50][16]
#define OFF_GH  2928   // 3200: [(p,j) -> (p*200+j)*2]
#define OFF_GX  6128   // 2 x 3200 double buffer
#define SMEM_FLOATS 12528
// fc smem
#define FOFF_W  0
#define FOFF_B  2512
#define FOFF_H  2576   // [50][16]

__device__ __forceinline__ float sigf(float x) {
    return __fdividef(1.0f, 1.0f + __expf(-x));
}
__device__ __forceinline__ float tanhfast(float x) {
    return 1.0f - __fdividef(2.0f, __expf(2.0f * x) + 1.0f);
}
__device__ __forceinline__ unsigned long long pack2(float x) {
    unsigned long long r;
    asm("mov.b64 %0, {%1, %1};" : "=l"(r) : "f"(x));
    return r;
}
__device__ __forceinline__ void fma2(unsigned long long& d, unsigned long long a,
                                     unsigned long long b) {
    asm("fma.rn.f32x2 %0, %1, %2, %0;" : "+l"(d) : "l"(a), "l"(b));
}
__device__ __forceinline__ int ld_acquire_gpu(const int* p) {
    int v;
    asm volatile("ld.acquire.gpu.global.b32 %0, [%1];" : "=r"(v) : "l"(p) : "memory");
    return v;
}
__device__ __forceinline__ void st_release_gpu(int* p, int v) {
    asm volatile("st.release.gpu.global.b32 [%0], %1;" :: "l"(p), "r"(v) : "memory");
}

#define BAR_SYNC(id, n)   asm volatile("bar.sync %0, %1;"   :: "r"(id), "r"(n) : "memory")
#define BAR_ARRIVE(id, n) asm volatile("bar.arrive %0, %1;" :: "r"(id), "r"(n) : "memory")

__global__ void xpose_kernel(const float* __restrict__ x) {
    if (blockIdx.x == 0 && threadIdx.x < NSL * NL) {
        d_prog[threadIdx.x] = 0;
        d_cons[threadIdx.x] = 0;
    }
    int idx = blockIdx.x * blockDim.x + threadIdx.x;  // (b*DIN+d)*T + t
    if (idx >= BATCH * DIN * TT) return;
    int t = idx % TT;
    int bd = idx / TT;
    int d = bd % DIN, b = bd / DIN;
    d_xT[(((size_t)t * NSL + b / BS) * DIN + d) * BS + (b % BS)] = x[idx];
}

__global__ void __launch_bounds__(TPB, 1) lstm_kernel(
    const float* __restrict__ hn,  const float* __restrict__ cn,
    const float* __restrict__ Wih0, const float* __restrict__ Wih,
    const float* __restrict__ Whh, const float* __restrict__ bih,
    const float* __restrict__ bhh, const float* __restrict__ fcw,
    const float* __restrict__ fcb, float* __restrict__ out, int has_state)
{
    extern __shared__ float sm[];
    const int tid  = threadIdx.x;
    const int lane = tid & 31;

    // ================= FC consumer role (blocks 128,129) =================
    if (blockIdx.x >= NL * NSL) {
        const int s = blockIdx.x - NL * NSL;
        float* sm_w  = sm + FOFF_W;
        float* sm_fb = sm + FOFF_B;
        float* sm_h  = sm + FOFF_H;
        for (int i = tid; i < DOUT * HH; i += TPB) sm_w[i] = fcw[i];
        for (int i = tid; i < DOUT; i += TPB)      sm_fb[i] = fcb[i];
        __syncthreads();
        const int* prog63 = &d_prog[s * NL + NL - 1];
        for (int t = 0; t < TT; ++t) {
            if (lane == 0) { while (ld_acquire_gpu(prog63) < t + 1) __nanosleep(128); }
            __syncwarp();
            const float* hp = d_hT + ((size_t)t * NSL + s) * HH * BS;
            for (int idx = tid; idx < HH * 4; idx += TPB) {
                float4 v = __ldcg((const float4*)(hp + idx * 4));
                *(float4*)(sm_h + idx * 4) = v;
            }
            __syncthreads();
            if (tid < G4) {
                const int o  = tid % DOUT;
                const int bq = tid / DOUT;
#pragma unroll
                for (int i = 0; i < 4; ++i) {
                    int b = bq * 4 + i;
                    float acc = sm_fb[o];
#pragma unroll 5
                    for (int u = 0; u < HH; ++u)
                        acc = fmaf(sm_h[u * BS + b], sm_w[o * HH + u], acc);
                    out[((size_t)(s * BS + b) * DOUT + o) * TT + t] = sigf(acc);
                }
            }
            __syncthreads();
        }
        return;
    }

    // ========================= LSTM layer role =========================
    const int  layer = blockIdx.x >> 1;
    const int  s     = blockIdx.x & 1;
    const int  b0    = s * BS;
    const int  K1    = (layer == 0) ? DIN : HH;
    const bool isX   = (tid >= 224);
    const int  j     = isX ? (tid - 224) : tid;   // gate row; active if < 200
    const bool act   = (j < G4);

    float* sm_b  = sm + OFF_B;
    float* sm_hs = sm + OFF_HS;
    float* sm_gh = sm + OFF_GH;

    // ---- init: zero xs (both buffers), bias, h0 ----
    for (int i = tid; i < 2 * DIN * BS; i += TPB) sm[OFF_XS + i] = 0.0f;
    for (int jj = tid; jj < G4; jj += TPB)
        sm_b[jj] = bih[layer * G4 + jj] + bhh[layer * G4 + jj];
    for (int idx = tid; idx < HH * BS; idx += TPB) {
        int u = idx / BS, b = idx % BS;
        sm_hs[u * BS + b] = hn[((size_t)layer * BATCH + b0 + b) * HH + u];
    }

    // ---- weights into regs: ONE gate-row column per thread ----
    float w[60];
    if (act) {
        if (isX) {
            const float* wg = (layer == 0) ? Wih0 : (Wih + (size_t)(layer - 1) * G4 * HH);
#pragma unroll
            for (int k = 0; k < 60; ++k)
                w[k] = (k < K1) ? wg[j * K1 + k] : 0.0f;
        } else {
            const float* wh = Whh + (size_t)layer * G4 * HH;
#pragma unroll
            for (int k = 0; k < 50; ++k)
                w[k] = wh[j * HH + k];
        }
    }

    // ---- cell state in regs (H-group C threads): tid<200: (u, bq) -> 4 batches ----
    float creg[4];
    const int u_c  = tid % HH;
    const int bq_c = (!isX && act) ? (tid / HH) : 0;   // 0..3
    if (!isX && act) {
#pragma unroll
        for (int i = 0; i < 4; ++i)
            creg[i] = cn[((size_t)layer * BATCH + b0 + 4 * bq_c + i) * HH + u_c];
    }
    __syncthreads();

    int* prog_prev = (layer > 0)      ? &d_prog[s * NL + layer - 1] : 0;
    int* cons_next = (layer < NL - 1) ? &d_cons[s * NL + layer + 1] : 0;
    int* prog_me   = &d_prog[s * NL + layer];
    int* cons_me   = &d_cons[s * NL + layer];

    if (!isX) {
        // ======================= H-group (warps 0-6) =======================
        for (int t = 0; t < TT; ++t) {
            // ---- B1: gh = bias + h @ Whh^T ----
            if (act) {
                unsigned long long acc2[8];
                unsigned long long b2 = pack2(sm_b[j]);
#pragma unroll
                for (int p = 0; p < 8; ++p) acc2[p] = b2;
#pragma unroll
                for (int k = 0; k < 50; ++k) {
                    unsigned long long w2 = pack2(w[k]);
                    const ulonglong2* hp = (const ulonglong2*)(sm_hs + k * BS);
                    ulonglong2 q0 = hp[0], q1 = hp[1], q2 = hp[2], q3 = hp[3];
                    fma2(acc2[0], q0.x, w2); fma2(acc2[1], q0.y, w2);
                    fma2(acc2[2], q1.x, w2); fma2(acc2[3], q1.y, w2);
                    fma2(acc2[4], q2.x, w2); fma2(acc2[5], q2.y, w2);
                    fma2(acc2[6], q3.x, w2); fma2(acc2[7], q3.y, w2);
                }
#pragma unroll
                for (int p = 0; p < 8; ++p)
                    *(unsigned long long*)(sm_gh + (p * G4 + j) * 2) = acc2[p];
            }

            // ---- wait gx(t) ready (parity barrier 2/3) ----
            BAR_SYNC(2 + (t & 1), TPB);

            // ---- ring backpressure before C's ring stores (uniform in H) ----
            if (layer < NL - 1 && t >= RINGN) {
                if (lane == 0) { while (ld_acquire_gpu(cons_next) < t - RINGN + 1) __nanosleep(32); }
                __syncwarp();
            }

            // ---- C: gates -> c,h (tid<200; 4 batches each) ----
            if (act) {
                const float* gx = sm + OFF_GX + (t & 1) * 3200;
                float h4[4];
#pragma unroll
                for (int i = 0; i < 4; ++i) {
                    int b    = 4 * bq_c + i;
                    int base = (b >> 1) * G4 * 2 + (b & 1);
                    float gi = gx[base + u_c * 2]         + sm_gh[base + u_c * 2];
                    float gf = gx[base + (50 + u_c) * 2]  + sm_gh[base + (50 + u_c) * 2];
                    float gg = gx[base + (100 + u_c) * 2] + sm_gh[base + (100 + u_c) * 2];
                    float go = gx[base + (150 + u_c) * 2] + sm_gh[base + (150 + u_c) * 2];
                    float c = sigf(gf) * creg[i] + sigf(gi) * tanhfast(gg);
                    float h = sigf(go) * tanhfast(c);
                    creg[i] = c;
                    h4[i] = h;
                }
                float4 hv = make_float4(h4[0], h4[1], h4[2], h4[3]);
                *(float4*)(sm_hs + u_c * BS + 4 * bq_c) = hv;
                float* dst = (layer < NL - 1)
                    ? (d_ring + (((size_t)layer * RINGN + (t & (RINGN - 1))) * NSL + s) * HH * BS
                       + u_c * BS + 4 * bq_c)
                    : (d_hT + ((size_t)t * NSL + s) * HH * BS + u_c * BS + 4 * bq_c);
                __stcg((float4*)dst, hv);
                if (t == TT - 1 && has_state) {
                    size_t base2 = (size_t)BATCH * DOUT * TT;
#pragma unroll
                    for (int i = 0; i < 4; ++i) {
                        size_t sidx = ((size_t)layer * BATCH + b0 + 4 * bq_c + i) * HH + u_c;
                        out[base2 + sidx] = h4[i];
                        out[base2 + (size_t)NL * BATCH * HH + sidx] = creg[i];
                    }
                }
            }
            BAR_ARRIVE(4 + (t & 1), TPB);   // gx[t&1] consumed (parity barrier 4/5)
            BAR_SYNC(6, 224);               // h(t) visible to all H before B1(t+1)
            if (tid == 0) st_release_gpu(prog_me, t + 1);
        }
    } else {
        // ======================= X-group (warps 7-13) =======================
        for (int t = 0; t < TT; ++t) {
            // gx[t&1] buffer free: pairs with H's arrive at t-2 on same parity
            if (t >= 2) BAR_SYNC(4 + (t & 1), TPB);
            if (layer > 0) {
                if (lane == 0) { while (ld_acquire_gpu(prog_prev) < t + 1) __nanosleep(32); }
                __syncwarp();
            }
            float* xbuf = sm + OFF_XS + (t & 1) * (DIN * BS);
            if (layer == 0) {
                const float* xp = d_xT + ((size_t)t * NSL + s) * DIN * BS;
                for (int idx = tid - 224; idx < DIN * 4; idx += 224) {
                    float4 v = *(const float4*)(xp + idx * 4);
                    *(float4*)(xbuf + idx * 4) = v;
                }
            } else {
                const float* rp = d_ring +
                    (((size_t)(layer - 1) * RINGN + (t & (RINGN - 1))) * NSL + s) * HH * BS;
                for (int idx = tid - 224; idx < HH * 4; idx += 224) {
                    float4 v = __ldcg((const float4*)(rp + idx * 4));
                    *(float4*)(xbuf + idx * 4) = v;
                }
            }
            BAR_SYNC(7, 224);                      // x staged (X-group only)
            if (tid == 224 && layer > 0 && (((t & 3) == 3) || t == TT - 1))
                st_release_gpu(cons_me, t + 1);

            if (act) {
                unsigned long long acc2[8];
#pragma unroll
                for (int p = 0; p < 8; ++p) acc2[p] = 0ull;
#pragma unroll
                for (int k = 0; k < 60; ++k) {
                    unsigned long long w2 = pack2(w[k]);
                    const ulonglong2* xp2 = (const ulonglong2*)(xbuf + k * BS);
                    ulonglong2 q0 = xp2[0], q1 = xp2[1], q2 = xp2[2], q3 = xp2[3];
                    fma2(acc2[0], q0.x, w2); fma2(acc2[1], q0.y, w2);
                    fma2(acc2[2], q1.x, w2); fma2(acc2[3], q1.y, w2);
                    fma2(acc2[4], q2.x, w2); fma2(acc2[5], q2.y, w2);
                    fma2(acc2[6], q3.x, w2); fma2(acc2[7], q3.y, w2);
                }
                float* gx = sm + OFF_GX + (t & 1) * 3200;
#pragma unroll
                for (int p = 0; p < 8; ++p)
                    *(unsigned long long*)(gx + (p * G4 + j) * 2) = acc2[p];
            }
            BAR_ARRIVE(2 + (t & 1), TPB);          // gx(t) ready
        }
    }
}

extern "C" void kernel_launch(void* const* d_in, const int* in_sizes, int n_in,
                              void* d_out, int out_size) {
    const float* x    = (const float*)d_in[0];
    const float* hn   = (const float*)d_in[1];
    const float* cn   = (const float*)d_in[2];
    const float* Wih0 = (const float*)d_in[3];
    const float* Wih  = (const float*)d_in[4];
    const float* Whh  = (const float*)d_in[5];
    const float* bih  = (const float*)d_in[6];
    const float* bhh  = (const float*)d_in[7];
    const float* fcw  = (const float*)d_in[8];
    const float* fcb  = (const float*)d_in[9];
    float* out = (float*)d_out;

    const long long full = (long long)BATCH * DOUT * TT + 2LL * NL * BATCH * HH;
    int has_state = (out_size >= full) ? 1 : 0;

    cudaFuncSetAttribute(lstm_kernel, cudaFuncAttributeMaxDynamicSharedMemorySize,
                         SMEM_FLOATS * sizeof(float));

    xpose_kernel<<<(BATCH * DIN * TT + 255) / 256, 256>>>(x);
    lstm_kernel<<<NL * NSL + NSL, TPB, SMEM_FLOATS * sizeof(float)>>>(
        hn, cn, Wih0, Wih, Whh, bih, bhh, fcw, fcb, out, has_state);
}